// round 3
// baseline (speedup 1.0000x reference)
#include <cuda_runtime.h>

#define NR 1024
#define NC 1024
#define NN (NR*NC)

// Dense per-destination stencil weights, planar [offset][node].
__device__ float g_W[8 * NN];   // 32 MB
__device__ float g_u[2][NN];    // ping-pong stage arguments
__device__ float g_k[5][NN];    // k1..k5 (k6 is consumed locally in stage 6)
__device__ float g_y[NN];       // current state y

// Tsit5 coefficients
#define DT (1.0f/32.0f)
#define A21  0.161f
#define A31 -0.008480655492356989f
#define A32  0.335480655492357f
#define A41  2.8971530571054935f
#define A42 -6.359448489975075f
#define A43  4.3622954328695815f
#define A51  5.325864828439257f
#define A52 -11.748883564062828f
#define A53  7.4955393428898365f
#define A54 -0.09249506636175525f
#define A61  5.86145544294642f
#define A62 -12.92096931784711f
#define A63  8.159367898576159f
#define A64 -0.071584973281401f
#define A65 -0.028269050394068383f
#define B1   0.09646076681806523f
#define B2   0.01f
#define B3   0.4798896504144996f
#define B4   1.379008574103742f
#define B5  -3.290069515436081f
#define B6   2.324710524099774f

// y0 = x, W = 0
__global__ void init_kernel(const float* __restrict__ x) {
    int i = blockIdx.x * blockDim.x + threadIdx.x;
    if (i >= NN) return;
    g_y[i] = x[i];
#pragma unroll
    for (int o = 0; o < 8; o++) g_W[o * NN + i] = 0.0f;
}

// Scatter edge weights into dense planes keyed by (dst, dst-src offset).
__global__ void scatter_W(const float* __restrict__ k,
                          const int* __restrict__ src,
                          const int* __restrict__ dst, int ne) {
    int e = blockIdx.x * blockDim.x + threadIdx.x;
    if (e >= ne) return;
    int j = src[e], i = dst[e];
    int dr = (i >> 10) - (j >> 10);      // pos(dst) - pos(src)
    int dc = (i & 1023) - (j & 1023);
    int idx = (dr + 1) * 3 + (dc + 1);   // 0..8, center (4) never occurs
    int o = (idx > 4) ? idx - 1 : idx;   // 0..7
    g_W[o * NN + i] = k[e];
}

__device__ __forceinline__ float act(float v) {
    return fminf(1.0f, fmaxf(-1.0f, v));
}

// Stage S: reads u_S, computes k_S = f(u_S); fuses the next-argument (or final
// B-) combination since it is elementwise at node i.
// ubuf codes: -1 => g_y, 0/1 => g_u[.]
template<int S>
__global__ void __launch_bounds__(512) stage_kernel(int ubuf_in, int ubuf_out,
                                                    const float* __restrict__ z) {
    int i = blockIdx.x * blockDim.x + threadIdx.x;
    if (i >= NN) return;

    const float* __restrict__ u_in  = (ubuf_in  < 0) ? g_y : g_u[ubuf_in];
    float*       __restrict__ u_out = (ubuf_out < 0) ? g_y : g_u[ubuf_out];

    float ui = u_in[i];

    // offs[o] = (dr*NC + dc) of (dst - src) for plane o.
    // Neighbor (source) index is j = i - offs[o].
    const int offs[8] = {-NC-1, -NC, -NC+1, -1, 1, NC-1, NC, NC+1};
    float sum = 0.0f;
#pragma unroll
    for (int o = 0; o < 8; o++) {
        int j = i - offs[o];
        if ((unsigned)j >= (unsigned)NN) j = 0;  // clamped; weight is 0 there
        sum = fmaf(g_W[o * NN + i], act(__ldg(&u_in[j])), sum);
    }
    float ks = -ui + z[i] + sum;

    float y = (S == 1) ? ui : g_y[i];

    if (S == 1) {
        g_k[0][i] = ks;
        u_out[i] = fmaf(DT, A21 * ks, y);
    } else if (S == 2) {
        float k1 = g_k[0][i];
        g_k[1][i] = ks;
        u_out[i] = fmaf(DT, A31 * k1 + A32 * ks, y);
    } else if (S == 3) {
        float k1 = g_k[0][i], k2 = g_k[1][i];
        g_k[2][i] = ks;
        u_out[i] = fmaf(DT, A41 * k1 + A42 * k2 + A43 * ks, y);
    } else if (S == 4) {
        float k1 = g_k[0][i], k2 = g_k[1][i], k3 = g_k[2][i];
        g_k[3][i] = ks;
        u_out[i] = fmaf(DT, A51 * k1 + A52 * k2 + A53 * k3 + A54 * ks, y);
    } else if (S == 5) {
        float k1 = g_k[0][i], k2 = g_k[1][i], k3 = g_k[2][i], k4 = g_k[3][i];
        g_k[4][i] = ks;
        u_out[i] = fmaf(DT, A61 * k1 + A62 * k2 + A63 * k3 + A64 * k4 + A65 * ks, y);
    } else { // S == 6: final combination -> new y
        float k1 = g_k[0][i], k2 = g_k[1][i], k3 = g_k[2][i], k4 = g_k[3][i], k5 = g_k[4][i];
        u_out[i] = fmaf(DT, B1*k1 + B2*k2 + B3*k3 + B4*k4 + B5*k5 + B6*ks, y);
    }
}

__global__ void clip_out_kernel(float* __restrict__ out) {
    int i = blockIdx.x * blockDim.x + threadIdx.x;
    if (i >= NN) return;
    out[i] = fminf(1.0f, fmaxf(-1.0f, g_y[i]));
}

extern "C" void kernel_launch(void* const* d_in, const int* in_sizes, int n_in,
                              void* d_out, int out_size) {
    const float* x   = (const float*)d_in[0];
    const float* z   = (const float*)d_in[1];
    const float* k   = (const float*)d_in[2];
    const int*   src = (const int*)d_in[3];
    const int*   dst = (const int*)d_in[4];
    int ne = in_sizes[2];

    const int T = 512;
    const int B = (NN + T - 1) / T;

    init_kernel<<<B, T>>>(x);
    scatter_W<<<(ne + T - 1) / T, T>>>(k, src, dst, ne);

    for (int step = 0; step < 32; step++) {
        stage_kernel<1><<<B, T>>>(-1, 0, z);  // u1 = y      -> k1, u2
        stage_kernel<2><<<B, T>>>( 0, 1, z);  // u2          -> k2, u3
        stage_kernel<3><<<B, T>>>( 1, 0, z);  // u3          -> k3, u4
        stage_kernel<4><<<B, T>>>( 0, 1, z);  // u4          -> k4, u5
        stage_kernel<5><<<B, T>>>( 1, 0, z);  // u5          -> k5, u6
        stage_kernel<6><<<B, T>>>( 0, -1, z); // u6          -> y_new (in place)
    }

    clip_out_kernel<<<B, T>>>((float*)d_out);
}

// round 4
// speedup vs baseline: 1.0456x; 1.0456x over previous
#include <cuda_runtime.h>

#define NR 1024
#define NC 1024
#define NN (NR*NC)

#define TS   32              // output tile side
#define H    6               // halo (6 one-ring stages)
#define REG  44              // TS + 2*H
#define REG2 (REG*REG)
#define RW   42              // fixed compute region width [1, 43)
#define RPTS (RW*RW)         // 1764
#define NTHR 1024

// persistent scratch
__device__ float g_W[8 * NN];   // dense stencil weights, planar [offset][node]
__device__ float g_yA[NN];
__device__ float g_yB[NN];

// Tsit5 coefficients
#define DT (1.0f/32.0f)
#define A21  0.161f
#define A31 -0.008480655492356989f
#define A32  0.335480655492357f
#define A41  2.8971530571054935f
#define A42 -6.359448489975075f
#define A43  4.3622954328695815f
#define A51  5.325864828439257f
#define A52 -11.748883564062828f
#define A53  7.4955393428898365f
#define A54 -0.09249506636175525f
#define A61  5.86145544294642f
#define A62 -12.92096931784711f
#define A63  8.159367898576159f
#define A64 -0.071584973281401f
#define A65 -0.028269050394068383f
#define B1   0.09646076681806523f
#define B2   0.01f
#define B3   0.4798896504144996f
#define B4   1.379008574103742f
#define B5  -3.290069515436081f
#define B6   2.324710524099774f

__device__ __forceinline__ float act(float v) {
    // fmaxf/fminf drop NaN operands -> sanitizes halo garbage too
    return fminf(1.0f, fmaxf(-1.0f, v));
}

__global__ void init_kernel(const float* __restrict__ x) {
    int i = blockIdx.x * blockDim.x + threadIdx.x;
    if (i >= NN) return;
    g_yA[i] = x[i];
#pragma unroll
    for (int o = 0; o < 8; o++) g_W[o * NN + i] = 0.0f;
}

// Scatter edge weights into dense planes keyed by (dst, dst-src offset).
__global__ void scatter_W(const float* __restrict__ k,
                          const int* __restrict__ src,
                          const int* __restrict__ dst, int ne) {
    int e = blockIdx.x * blockDim.x + threadIdx.x;
    if (e >= ne) return;
    int j = src[e], i = dst[e];
    int dr = (i >> 10) - (j >> 10);      // pos(dst) - pos(src)
    int dc = (i & 1023) - (j & 1023);
    int idx = (dr + 1) * 3 + (dc + 1);   // 0..8, center (4) never occurs
    int o = (idx > 4) ? idx - 1 : idx;   // 0..7
    g_W[o * NN + i] = k[e];
}

// One stage: k_S = f(u_cur) at the fixed region, then the elementwise combo
// for the next stage argument (or the final B-combination at stage 6).
template<int S>
__device__ __forceinline__ void stage(const float* __restrict__ uc,
                                      float* __restrict__ un,
                                      float w[2][8], float kk[2][5],
                                      const float yv[2], const float zv[2],
                                      const int sp[2], const int gg[2],
                                      const bool inner[2],
                                      float* __restrict__ y_out,
                                      float* __restrict__ fin) {
#pragma unroll
    for (int it = 0; it < 2; it++) {
        int p = sp[it];
        if (p < 0) continue;
        float s = zv[it] - uc[p];
        // weight plane o pairs with source neighbor j = p - loff[o]
        s = fmaf(w[it][0], act(uc[p + REG + 1]), s);
        s = fmaf(w[it][1], act(uc[p + REG    ]), s);
        s = fmaf(w[it][2], act(uc[p + REG - 1]), s);
        s = fmaf(w[it][3], act(uc[p + 1      ]), s);
        s = fmaf(w[it][4], act(uc[p - 1      ]), s);
        s = fmaf(w[it][5], act(uc[p - REG + 1]), s);
        s = fmaf(w[it][6], act(uc[p - REG    ]), s);
        s = fmaf(w[it][7], act(uc[p - REG - 1]), s);

        if (S == 1) { kk[it][0] = s; un[p] = fmaf(DT, A21 * s, yv[it]); }
        if (S == 2) { kk[it][1] = s; un[p] = fmaf(DT, A31*kk[it][0] + A32*s, yv[it]); }
        if (S == 3) { kk[it][2] = s; un[p] = fmaf(DT, A41*kk[it][0] + A42*kk[it][1] + A43*s, yv[it]); }
        if (S == 4) { kk[it][3] = s; un[p] = fmaf(DT, A51*kk[it][0] + A52*kk[it][1] + A53*kk[it][2] + A54*s, yv[it]); }
        if (S == 5) { kk[it][4] = s; un[p] = fmaf(DT, A61*kk[it][0] + A62*kk[it][1] + A63*kk[it][2] + A64*kk[it][3] + A65*s, yv[it]); }
        if (S == 6) {
            if (inner[it]) {
                float yn = fmaf(DT, B1*kk[it][0] + B2*kk[it][1] + B3*kk[it][2]
                                  + B4*kk[it][3] + B5*kk[it][4] + B6*s, yv[it]);
                if (fin) fin[gg[it]] = fminf(1.0f, fmaxf(-1.0f, yn));
                else     y_out[gg[it]] = yn;
            }
        }
    }
    __syncthreads();
}

// One full Tsit5 step for a 32x32 tile with halo-6 redundant compute.
__global__ void __launch_bounds__(NTHR, 1)
step_kernel(int par, const float* __restrict__ z, float* __restrict__ fin) {
    __shared__ float sy[REG2];
    __shared__ float uA[REG2];
    __shared__ float uB[REG2];

    const float* __restrict__ y_in  = par ? g_yB : g_yA;
    float*       __restrict__ y_out = par ? g_yA : g_yB;

    const int tid = threadIdx.x;
    const int r0 = (int)blockIdx.y * TS - H;
    const int c0 = (int)blockIdx.x * TS - H;

    // load y tile (zero-padded OOB); zero-init u ping-pong buffers
    for (int p = tid; p < REG2; p += NTHR) {
        int lr = p / REG, lc = p - lr * REG;
        int r = r0 + lr, c = c0 + lc;
        bool in = ((unsigned)r < NR) & ((unsigned)c < NC);
        sy[p] = in ? y_in[r * NC + c] : 0.0f;
        uA[p] = 0.0f;
        uB[p] = 0.0f;
    }

    // per-thread fixed point assignment (2 points) with register-resident state
    float w[2][8], kk[2][5], yv[2], zv[2];
    int   sp[2], gg[2];
    bool  inner[2];

#pragma unroll
    for (int it = 0; it < 2; it++) {
        int pl = tid + it * NTHR;
        bool valid = pl < RPTS;
        int lr = 1 + pl / RW;
        int lc = 1 + (pl - (lr - 1) * RW);
        int r = r0 + lr, c = c0 + lc;
        bool in = valid & ((unsigned)r < NR) & ((unsigned)c < NC);
        int g = in ? (r * NC + c) : 0;
        sp[it]    = valid ? lr * REG + lc : -1;
        gg[it]    = g;
        inner[it] = valid & (lr >= H) & (lr < H + TS) & (lc >= H) & (lc < H + TS);
        zv[it]    = in ? z[g] : 0.0f;
#pragma unroll
        for (int o = 0; o < 8; o++)
            w[it][o] = in ? g_W[o * NN + g] : 0.0f;
    }
    __syncthreads();

#pragma unroll
    for (int it = 0; it < 2; it++)
        yv[it] = (sp[it] >= 0) ? sy[sp[it]] : 0.0f;

    stage<1>(sy, uA, w, kk, yv, zv, sp, gg, inner, y_out, fin);
    stage<2>(uA, uB, w, kk, yv, zv, sp, gg, inner, y_out, fin);
    stage<3>(uB, uA, w, kk, yv, zv, sp, gg, inner, y_out, fin);
    stage<4>(uA, uB, w, kk, yv, zv, sp, gg, inner, y_out, fin);
    stage<5>(uB, uA, w, kk, yv, zv, sp, gg, inner, y_out, fin);
    stage<6>(uA, uB, w, kk, yv, zv, sp, gg, inner, y_out, fin);
}

extern "C" void kernel_launch(void* const* d_in, const int* in_sizes, int n_in,
                              void* d_out, int out_size) {
    const float* x   = (const float*)d_in[0];
    const float* z   = (const float*)d_in[1];
    const float* k   = (const float*)d_in[2];
    const int*   src = (const int*)d_in[3];
    const int*   dst = (const int*)d_in[4];
    int ne = in_sizes[2];

    init_kernel<<<(NN + 511) / 512, 512>>>(x);
    scatter_W<<<(ne + 511) / 512, 512>>>(k, src, dst, ne);

    dim3 grid(NC / TS, NR / TS);   // 32 x 32 tiles
    for (int s = 0; s < 32; s++) {
        float* fin = (s == 31) ? (float*)d_out : nullptr;  // last step: fused clip -> d_out
        step_kernel<<<grid, NTHR>>>(s & 1, z, fin);
    }
}

// round 5
// speedup vs baseline: 1.1614x; 1.1107x over previous
#include <cuda_runtime.h>

#define NR 1024
#define NC 1024
#define NN (NR*NC)

#define TS   32              // output tile side
#define H    6               // halo (6 one-ring stages)
#define REG  44              // TS + 2*H
#define REG2 (REG*REG)
#define NPR  21              // column-pairs per region row
#define NROWS 42             // region rows [1,43)
#define NPAIR (NPR*NROWS)    // 882
#define NTHR 896

// persistent scratch
__device__ float g_W[8 * NN];   // dense stencil weights, planar [offset][node]
__device__ float g_yA[NN];
__device__ float g_yB[NN];

// Tsit5 coefficients
#define DT (1.0f/32.0f)
#define A21  0.161f
#define A31 -0.008480655492356989f
#define A32  0.335480655492357f
#define A41  2.8971530571054935f
#define A42 -6.359448489975075f
#define A43  4.3622954328695815f
#define A51  5.325864828439257f
#define A52 -11.748883564062828f
#define A53  7.4955393428898365f
#define A54 -0.09249506636175525f
#define A61  5.86145544294642f
#define A62 -12.92096931784711f
#define A63  8.159367898576159f
#define A64 -0.071584973281401f
#define A65 -0.028269050394068383f
#define B1   0.09646076681806523f
#define B2   0.01f
#define B3   0.4798896504144996f
#define B4   1.379008574103742f
#define B5  -3.290069515436081f
#define B6   2.324710524099774f

__device__ __forceinline__ float act(float v) {
    // fmaxf/fminf drop NaN operands -> sanitizes halo garbage too
    return fminf(1.0f, fmaxf(-1.0f, v));
}

__global__ void init_kernel(const float* __restrict__ x) {
    int i = blockIdx.x * blockDim.x + threadIdx.x;
    if (i >= NN) return;
    g_yA[i] = x[i];
#pragma unroll
    for (int o = 0; o < 8; o++) g_W[o * NN + i] = 0.0f;
}

// Scatter edge weights into dense planes keyed by (dst, dst-src offset).
__global__ void scatter_W(const float* __restrict__ k,
                          const int* __restrict__ src,
                          const int* __restrict__ dst, int ne) {
    int e = blockIdx.x * blockDim.x + threadIdx.x;
    if (e >= ne) return;
    int j = src[e], i = dst[e];
    int dr = (i >> 10) - (j >> 10);      // pos(dst) - pos(src)
    int dc = (i & 1023) - (j & 1023);
    int idx = (dr + 1) * 3 + (dc + 1);   // 0..8, center (4) never occurs
    int o = (idx > 4) ? idx - 1 : idx;   // 0..7
    g_W[o * NN + i] = k[e];
}

// One stage for a horizontally-adjacent point pair (A at p, B at p+1), lc odd.
// Weight plane o (offset = dst-src) pairs with source neighbor at p - loff[o].
template<int S>
__device__ __forceinline__ void do_stage(
    const float* __restrict__ uc, float* __restrict__ un,
    bool valid, int p,
    const float wA[8], const float wB[8],
    float kA[5], float kB[5],
    float yA, float yB, float zA, float zB,
    bool innA, bool innB, int gA, int gB,
    float* __restrict__ y_out, float* __restrict__ fin)
{
    if (valid) {
        // 3 rows x 4 cols neighborhood as 6 aligned float2 loads
        float2 am = *(const float2*)(uc + p - REG - 1);  // row-1, cols lc-1,lc
        float2 bm = *(const float2*)(uc + p - REG + 1);  // row-1, cols lc+1,lc+2
        float2 ac = *(const float2*)(uc + p       - 1);  // row  , cols lc-1,lc
        float2 bc = *(const float2*)(uc + p       + 1);  // row  , cols lc+1,lc+2
        float2 ap = *(const float2*)(uc + p + REG - 1);  // row+1, cols lc-1,lc
        float2 bp = *(const float2*)(uc + p + REG + 1);  // row+1, cols lc+1,lc+2

        float t_amx = act(am.x), t_amy = act(am.y), t_bmx = act(bm.x), t_bmy = act(bm.y);
        float t_acx = act(ac.x), t_acy = act(ac.y), t_bcx = act(bc.x), t_bcy = act(bc.y);
        float t_apx = act(ap.x), t_apy = act(ap.y), t_bpx = act(bp.x), t_bpy = act(bp.y);

        // Point A: center = ac.y (index p)
        float sA = zA - ac.y;
        sA = fmaf(wA[0], t_bpx, sA);   // src at p+REG+1
        sA = fmaf(wA[1], t_apy, sA);   // p+REG
        sA = fmaf(wA[2], t_apx, sA);   // p+REG-1
        sA = fmaf(wA[3], t_bcx, sA);   // p+1
        sA = fmaf(wA[4], t_acx, sA);   // p-1
        sA = fmaf(wA[5], t_bmx, sA);   // p-REG+1
        sA = fmaf(wA[6], t_amy, sA);   // p-REG
        sA = fmaf(wA[7], t_amx, sA);   // p-REG-1

        // Point B: center = bc.x (index p+1)
        float sB = zB - bc.x;
        sB = fmaf(wB[0], t_bpy, sB);   // p+REG+2
        sB = fmaf(wB[1], t_bpx, sB);   // p+REG+1
        sB = fmaf(wB[2], t_apy, sB);   // p+REG
        sB = fmaf(wB[3], t_bcy, sB);   // p+2
        sB = fmaf(wB[4], t_acy, sB);   // p
        sB = fmaf(wB[5], t_bmy, sB);   // p-REG+2
        sB = fmaf(wB[6], t_bmx, sB);   // p-REG+1
        sB = fmaf(wB[7], t_amy, sB);   // p-REG

        if (S == 1) {
            kA[0] = sA; kB[0] = sB;
            un[p]   = fmaf(DT, A21 * sA, yA);
            un[p+1] = fmaf(DT, A21 * sB, yB);
        } else if (S == 2) {
            kA[1] = sA; kB[1] = sB;
            un[p]   = fmaf(DT, A31*kA[0] + A32*sA, yA);
            un[p+1] = fmaf(DT, A31*kB[0] + A32*sB, yB);
        } else if (S == 3) {
            kA[2] = sA; kB[2] = sB;
            un[p]   = fmaf(DT, A41*kA[0] + A42*kA[1] + A43*sA, yA);
            un[p+1] = fmaf(DT, A41*kB[0] + A42*kB[1] + A43*sB, yB);
        } else if (S == 4) {
            kA[3] = sA; kB[3] = sB;
            un[p]   = fmaf(DT, A51*kA[0] + A52*kA[1] + A53*kA[2] + A54*sA, yA);
            un[p+1] = fmaf(DT, A51*kB[0] + A52*kB[1] + A53*kB[2] + A54*sB, yB);
        } else if (S == 5) {
            kA[4] = sA; kB[4] = sB;
            un[p]   = fmaf(DT, A61*kA[0] + A62*kA[1] + A63*kA[2] + A64*kA[3] + A65*sA, yA);
            un[p+1] = fmaf(DT, A61*kB[0] + A62*kB[1] + A63*kB[2] + A64*kB[3] + A65*sB, yB);
        } else { // S == 6: final B-combination -> global y (or clipped output)
            if (innA) {
                float yn = fmaf(DT, B1*kA[0] + B2*kA[1] + B3*kA[2]
                                  + B4*kA[3] + B5*kA[4] + B6*sA, yA);
                if (fin) fin[gA] = fminf(1.0f, fmaxf(-1.0f, yn));
                else     y_out[gA] = yn;
            }
            if (innB) {
                float yn = fmaf(DT, B1*kB[0] + B2*kB[1] + B3*kB[2]
                                  + B4*kB[3] + B5*kB[4] + B6*sB, yB);
                if (fin) fin[gB] = fminf(1.0f, fmaxf(-1.0f, yn));
                else     y_out[gB] = yn;
            }
        }
    }
}

// One full Tsit5 step for a 32x32 tile with halo-6 redundant compute.
// Thread owns a horizontally adjacent point pair; smem ping-pongs over 2 buffers.
__global__ void __launch_bounds__(NTHR)
step_kernel(int par, const float* __restrict__ z, float* __restrict__ fin) {
    __shared__ __align__(16) float sA_buf[REG2];   // holds y tile initially
    __shared__ __align__(16) float sB_buf[REG2];

    const float* __restrict__ y_in  = par ? g_yB : g_yA;
    float*       __restrict__ y_out = par ? g_yA : g_yB;

    const int tid = threadIdx.x;
    const int r0 = (int)blockIdx.y * TS - H;
    const int c0 = (int)blockIdx.x * TS - H;

    // load y tile (zero-padded OOB); zero-init the other buffer (finite halo ring)
    for (int p = tid; p < REG2; p += NTHR) {
        int lr = p / REG, lc = p - lr * REG;
        int r = r0 + lr, c = c0 + lc;
        bool in = ((unsigned)r < NR) & ((unsigned)c < NC);
        sA_buf[p] = in ? y_in[r * NC + c] : 0.0f;
        sB_buf[p] = 0.0f;
    }

    // per-thread pair assignment: row lr in [1,43), cols (lc, lc+1), lc odd
    const bool valid = tid < NPAIR;
    int pr = tid / NPR;
    int pc = tid - pr * NPR;
    int lr = 1 + pr;
    int lc = 1 + 2 * pc;
    int p  = lr * REG + lc;

    int rA = r0 + lr, cA = c0 + lc, cB = cA + 1;
    bool inA = valid & ((unsigned)rA < NR) & ((unsigned)cA < NC);
    bool inB = valid & ((unsigned)rA < NR) & ((unsigned)cB < NC);
    int gA = inA ? (rA * NC + cA) : 0;
    int gB = inB ? (rA * NC + cB) : 0;
    bool innA = valid & (lr >= H) & (lr < H + TS) & (lc   >= H) & (lc   < H + TS);
    bool innB = valid & (lr >= H) & (lr < H + TS) & (lc+1 >= H) & (lc+1 < H + TS);

    float zA = inA ? z[gA] : 0.0f;
    float zB = inB ? z[gB] : 0.0f;

    float wA[8], wB[8];
#pragma unroll
    for (int o = 0; o < 8; o++) {
        wA[o] = inA ? g_W[o * NN + gA] : 0.0f;
        wB[o] = inB ? g_W[o * NN + gB] : 0.0f;
    }
    __syncthreads();

    float yA = 0.0f, yB = 0.0f;
    if (valid) { yA = sA_buf[p]; yB = sA_buf[p + 1]; }

    float kA[5], kB[5];

    do_stage<1>(sA_buf, sB_buf, valid, p, wA, wB, kA, kB, yA, yB, zA, zB, innA, innB, gA, gB, y_out, fin);
    __syncthreads();
    do_stage<2>(sB_buf, sA_buf, valid, p, wA, wB, kA, kB, yA, yB, zA, zB, innA, innB, gA, gB, y_out, fin);
    __syncthreads();
    do_stage<3>(sA_buf, sB_buf, valid, p, wA, wB, kA, kB, yA, yB, zA, zB, innA, innB, gA, gB, y_out, fin);
    __syncthreads();
    do_stage<4>(sB_buf, sA_buf, valid, p, wA, wB, kA, kB, yA, yB, zA, zB, innA, innB, gA, gB, y_out, fin);
    __syncthreads();
    do_stage<5>(sA_buf, sB_buf, valid, p, wA, wB, kA, kB, yA, yB, zA, zB, innA, innB, gA, gB, y_out, fin);
    __syncthreads();
    do_stage<6>(sB_buf, sA_buf, valid, p, wA, wB, kA, kB, yA, yB, zA, zB, innA, innB, gA, gB, y_out, fin);
}

extern "C" void kernel_launch(void* const* d_in, const int* in_sizes, int n_in,
                              void* d_out, int out_size) {
    const float* x   = (const float*)d_in[0];
    const float* z   = (const float*)d_in[1];
    const float* k   = (const float*)d_in[2];
    const int*   src = (const int*)d_in[3];
    const int*   dst = (const int*)d_in[4];
    int ne = in_sizes[2];

    init_kernel<<<(NN + 511) / 512, 512>>>(x);
    scatter_W<<<(ne + 511) / 512, 512>>>(k, src, dst, ne);

    dim3 grid(NC / TS, NR / TS);   // 32 x 32 tiles
    for (int s = 0; s < 32; s++) {
        float* fin = (s == 31) ? (float*)d_out : nullptr;  // last step: fused clip -> d_out
        step_kernel<<<grid, NTHR>>>(s & 1, z, fin);
    }
}